// round 2
// baseline (speedup 1.0000x reference)
#include <cuda_runtime.h>
#include <cuda_bf16.h>
#include <math.h>

// Problem constants (fixed shapes from reference)
#define TT 512      // tokens
#define DD 1024     // model dim
#define FF 4096     // ffn dim
#define EE 8        // experts
#define RR 16       // lora rank
#define KK 2        // top-k
#define SCALE 2.0f  // lora_alpha / lora_r = 32/16
#define EPSV 1e-6f

// ------------------------------------------------------------------
// Scratch (static __device__ — no allocations allowed).
// Kernels reference these directly; no cudaGetSymbolAddress needed.
// ------------------------------------------------------------------
__device__ float g_t[TT * DD];            // normalized tokens        2 MB
__device__ float g_base[TT * 2 * FF];     // [t][0:F]=w1x, [t][F:2F]=w3x  16 MB
__device__ float g_act[TT * KK * FF];     // SwiGLU activations      16 MB
__device__ float g_down[TT * KK * DD];    // down-proj base result    4 MB
__device__ float g_c1[TT * KK * RR];
__device__ float g_c3[TT * KK * RR];
__device__ float g_c2[TT * KK * RR];
__device__ int   g_eidx[TT * KK];
__device__ float g_ew[TT * KK];

// ------------------------------------------------------------------
// K1: RMSNorm + router (softmax -> top-2 -> renorm)
// grid = TT blocks, 256 threads
// ------------------------------------------------------------------
__global__ __launch_bounds__(256) void k_norm_route(
    const float* __restrict__ x, const float* __restrict__ normw,
    const float* __restrict__ gatew)
{
    const int t = blockIdx.x, tid = threadIdx.x;
    const float* xr = x + (size_t)t * DD;

    float ss = 0.f;
    for (int i = tid; i < DD; i += 256) { float v = xr[i]; ss += v * v; }
    #pragma unroll
    for (int o = 16; o; o >>= 1) ss += __shfl_xor_sync(~0u, ss, o);

    __shared__ float sred[8];
    __shared__ float s_inv;
    if ((tid & 31) == 0) sred[tid >> 5] = ss;
    __syncthreads();
    if (tid == 0) {
        float tot = 0.f;
        #pragma unroll
        for (int i = 0; i < 8; i++) tot += sred[i];
        s_inv = rsqrtf(tot / (float)DD + EPSV);
    }
    __syncthreads();
    const float inv = s_inv;
    for (int i = tid; i < DD; i += 256)
        g_t[(size_t)t * DD + i] = xr[i] * inv * normw[i];
    __syncthreads();

    // router logits: one warp per expert
    const int w = tid >> 5, lane = tid & 31;
    const float* gw = gatew + (size_t)w * DD;
    const float* nx = g_t + (size_t)t * DD;
    float p = 0.f;
    for (int i = lane; i < DD; i += 32) p += nx[i] * gw[i];
    #pragma unroll
    for (int o = 16; o; o >>= 1) p += __shfl_xor_sync(~0u, p, o);

    __shared__ float slog[EE];
    if (lane == 0) slog[w] = p;
    __syncthreads();

    if (tid == 0) {
        float m = slog[0];
        #pragma unroll
        for (int i = 1; i < EE; i++) m = fmaxf(m, slog[i]);
        float ex[EE];
        #pragma unroll
        for (int i = 0; i < EE; i++) ex[i] = expf(slog[i] - m);
        // top-2 (first occurrence on ties, matching lax.top_k)
        int i0 = 0; float b0 = ex[0];
        #pragma unroll
        for (int i = 1; i < EE; i++) if (ex[i] > b0) { b0 = ex[i]; i0 = i; }
        int i1 = -1; float b1v = -1.f;
        #pragma unroll
        for (int i = 0; i < EE; i++)
            if (i != i0 && ex[i] > b1v) { b1v = ex[i]; i1 = i; }
        // softmax denominator cancels under renormalization
        const float s = b0 + b1v;
        g_eidx[t * 2 + 0] = i0;  g_ew[t * 2 + 0] = b0 / s;
        g_eidx[t * 2 + 1] = i1;  g_ew[t * 2 + 1] = b1v / s;
    }
}

// ------------------------------------------------------------------
// K2: Up-proj base GEMM.
// C[t][n] = g_t[t] . W[n]  where W row n is w1[n] (n<F) or w3[n-F].
// 128x128 tile, BK=16, 8x8 per thread, 256 threads.
// grid = (64, 4)
// ------------------------------------------------------------------
__global__ __launch_bounds__(256) void k_gemm_up(
    const float* __restrict__ w1, const float* __restrict__ w3)
{
    constexpr int BM = 128, BN = 128, BK = 16;
    __shared__ float As[BK][BM + 4];
    __shared__ float Bs[BK][BN + 4];

    const int tid = threadIdx.x;
    const int bm = blockIdx.y * BM;
    const int bn = blockIdx.x * BN;
    const int tx = tid % 16;       // 16 cols of threads * TN=8 = 128
    const int ty = tid / 16;       // 16 rows of threads * TM=8 = 128

    float acc[8][8];
    #pragma unroll
    for (int i = 0; i < 8; i++)
        #pragma unroll
        for (int j = 0; j < 8; j++) acc[i][j] = 0.f;

    for (int k0 = 0; k0 < DD; k0 += BK) {
        // Load A tile: 128 rows x 16 k. 256 threads x 8 elems, float4 x2.
        {
            const int r = tid >> 1;            // 0..127
            const int c4 = (tid & 1) * 8;      // 0 or 8
            const float4 v0 = *reinterpret_cast<const float4*>(
                &g_t[(size_t)(bm + r) * DD + k0 + c4]);
            const float4 v1 = *reinterpret_cast<const float4*>(
                &g_t[(size_t)(bm + r) * DD + k0 + c4 + 4]);
            As[c4 + 0][r] = v0.x; As[c4 + 1][r] = v0.y;
            As[c4 + 2][r] = v0.z; As[c4 + 3][r] = v0.w;
            As[c4 + 4][r] = v1.x; As[c4 + 5][r] = v1.y;
            As[c4 + 6][r] = v1.z; As[c4 + 7][r] = v1.w;
        }
        // Load B tile: 128 rows (n) x 16 k.
        {
            const int r = tid >> 1;
            const int c4 = (tid & 1) * 8;
            const int n = bn + r;
            const float* Brow = (n < FF) ? (w1 + (size_t)n * DD)
                                         : (w3 + (size_t)(n - FF) * DD);
            const float4 v0 = *reinterpret_cast<const float4*>(&Brow[k0 + c4]);
            const float4 v1 = *reinterpret_cast<const float4*>(&Brow[k0 + c4 + 4]);
            Bs[c4 + 0][r] = v0.x; Bs[c4 + 1][r] = v0.y;
            Bs[c4 + 2][r] = v0.z; Bs[c4 + 3][r] = v0.w;
            Bs[c4 + 4][r] = v1.x; Bs[c4 + 5][r] = v1.y;
            Bs[c4 + 6][r] = v1.z; Bs[c4 + 7][r] = v1.w;
        }
        __syncthreads();

        #pragma unroll
        for (int k = 0; k < BK; k++) {
            float ra[8], rb[8];
            #pragma unroll
            for (int q = 0; q < 2; q++) {
                float4 v = *reinterpret_cast<const float4*>(&As[k][ty * 8 + q * 4]);
                ra[q * 4 + 0] = v.x; ra[q * 4 + 1] = v.y;
                ra[q * 4 + 2] = v.z; ra[q * 4 + 3] = v.w;
            }
            #pragma unroll
            for (int q = 0; q < 2; q++) {
                float4 v = *reinterpret_cast<const float4*>(&Bs[k][tx * 8 + q * 4]);
                rb[q * 4 + 0] = v.x; rb[q * 4 + 1] = v.y;
                rb[q * 4 + 2] = v.z; rb[q * 4 + 3] = v.w;
            }
            #pragma unroll
            for (int i = 0; i < 8; i++)
                #pragma unroll
                for (int j = 0; j < 8; j++)
                    acc[i][j] = fmaf(ra[i], rb[j], acc[i][j]);
        }
        __syncthreads();
    }

    #pragma unroll
    for (int i = 0; i < 8; i++) {
        const size_t row = (size_t)(bm + ty * 8 + i) * (2 * FF) + bn + tx * 8;
        #pragma unroll
        for (int j = 0; j < 8; j += 4) {
            *reinterpret_cast<float4*>(&g_base[row + j]) =
                make_float4(acc[i][j], acc[i][j+1], acc[i][j+2], acc[i][j+3]);
        }
    }
}

// ------------------------------------------------------------------
// K3: up-proj LoRA coefficients  c1/c3[t][slot][r] = t . a{1,3}[e][r]
// grid = TT blocks, 256 threads (8 warps x 8 dots of 1024)
// ------------------------------------------------------------------
__global__ __launch_bounds__(256) void k_lora_up_coeff(
    const float* __restrict__ a1, const float* __restrict__ a3)
{
    const int t = blockIdx.x, tid = threadIdx.x;
    const int w = tid >> 5, lane = tid & 31;
    const float* nx = g_t + (size_t)t * DD;

    #pragma unroll
    for (int dj = 0; dj < 8; dj++) {
        const int dIdx = w * 8 + dj;           // 0..63
        const int slot = dIdx >> 5;            // 0/1
        const int mat  = (dIdx >> 4) & 1;      // 0 -> a1, 1 -> a3
        const int r    = dIdx & 15;
        const int e    = g_eidx[t * 2 + slot];
        const float* ar = (mat ? a3 : a1) + ((size_t)e * RR + r) * DD;
        float p = 0.f;
        for (int i = lane; i < DD; i += 32) p += nx[i] * ar[i];
        #pragma unroll
        for (int o = 16; o; o >>= 1) p += __shfl_xor_sync(~0u, p, o);
        if (lane == 0)
            (mat ? g_c3 : g_c1)[(size_t)(t * 2 + slot) * RR + r] = p;
    }
}

// ------------------------------------------------------------------
// K4: act[ts][f] = silu(base1 + SC*lora1) * (base3 + SC*lora3)
// grid = TT*KK blocks, 256 threads
// ------------------------------------------------------------------
__global__ __launch_bounds__(256) void k_act(
    const float* __restrict__ b1, const float* __restrict__ b3)
{
    const int ts = blockIdx.x, tid = threadIdx.x;
    const int t = ts >> 1;
    const int e = g_eidx[ts];

    __shared__ float c1s[RR], c3s[RR];
    if (tid < RR) c1s[tid] = g_c1[(size_t)ts * RR + tid];
    else if (tid < 2 * RR) c3s[tid - RR] = g_c3[(size_t)ts * RR + tid - RR];
    __syncthreads();

    for (int fi = tid; fi < FF; fi += 256) {
        const float4* B1 = reinterpret_cast<const float4*>(b1 + ((size_t)e * FF + fi) * RR);
        const float4* B3 = reinterpret_cast<const float4*>(b3 + ((size_t)e * FF + fi) * RR);
        float d1 = 0.f, d3 = 0.f;
        #pragma unroll
        for (int q = 0; q < 4; q++) {
            float4 v1 = B1[q], v3 = B3[q];
            d1 += v1.x * c1s[q * 4] + v1.y * c1s[q * 4 + 1]
                + v1.z * c1s[q * 4 + 2] + v1.w * c1s[q * 4 + 3];
            d3 += v3.x * c3s[q * 4] + v3.y * c3s[q * 4 + 1]
                + v3.z * c3s[q * 4 + 2] + v3.w * c3s[q * 4 + 3];
        }
        const float h1 = g_base[(size_t)t * (2 * FF) + fi] + SCALE * d1;
        const float h3 = g_base[(size_t)t * (2 * FF) + FF + fi] + SCALE * d3;
        const float sig = 1.f / (1.f + expf(-h1));
        g_act[(size_t)ts * FF + fi] = h1 * sig * h3;
    }
}

// ------------------------------------------------------------------
// K5: down-proj LoRA coefficients c2[ts][r] = act[ts] . a2[e][r]
// grid = TT*KK blocks, 256 threads (8 warps x 2 dots of 4096)
// ------------------------------------------------------------------
__global__ __launch_bounds__(256) void k_lora_down_coeff(
    const float* __restrict__ a2)
{
    const int ts = blockIdx.x, tid = threadIdx.x;
    const int w = tid >> 5, lane = tid & 31;
    const int e = g_eidx[ts];
    const float* ac = g_act + (size_t)ts * FF;

    #pragma unroll
    for (int jj = 0; jj < 2; jj++) {
        const int r = w * 2 + jj;
        const float* ar = a2 + ((size_t)e * RR + r) * FF;
        float p = 0.f;
        for (int i = lane; i < FF; i += 32) p += ac[i] * ar[i];
        #pragma unroll
        for (int o = 16; o; o >>= 1) p += __shfl_xor_sync(~0u, p, o);
        if (lane == 0) g_c2[(size_t)ts * RR + r] = p;
    }
}

// ------------------------------------------------------------------
// K6: Down-proj base GEMM.
// C[ts][d] = g_act[ts] . w2[d]   (w2 is [D, F] row-major, K-major rows)
// 64x64 tile, BK=16, 4x4 per thread, 256 threads. grid = (16, 16)
// ------------------------------------------------------------------
__global__ __launch_bounds__(256) void k_gemm_down(
    const float* __restrict__ w2)
{
    constexpr int BM = 64, BN = 64, BK = 16;
    __shared__ float As[BK][BM + 4];
    __shared__ float Bs[BK][BN + 4];

    const int tid = threadIdx.x;
    const int bm = blockIdx.y * BM;
    const int bn = blockIdx.x * BN;
    const int tx = tid % 16;       // 16 * TN=4 = 64
    const int ty = tid / 16;       // 16 * TM=4 = 64

    float acc[4][4];
    #pragma unroll
    for (int i = 0; i < 4; i++)
        #pragma unroll
        for (int j = 0; j < 4; j++) acc[i][j] = 0.f;

    for (int k0 = 0; k0 < FF; k0 += BK) {
        // A tile: 64 rows x 16 k = 1024 elems; 256 threads x 4 (one float4)
        {
            const int r = tid >> 2;           // 0..63
            const int c4 = (tid & 3) * 4;     // 0,4,8,12
            const float4 v = *reinterpret_cast<const float4*>(
                &g_act[(size_t)(bm + r) * FF + k0 + c4]);
            As[c4 + 0][r] = v.x; As[c4 + 1][r] = v.y;
            As[c4 + 2][r] = v.z; As[c4 + 3][r] = v.w;
        }
        // B tile: 64 rows (d) x 16 k
        {
            const int r = tid >> 2;
            const int c4 = (tid & 3) * 4;
            const float4 v = *reinterpret_cast<const float4*>(
                &w2[(size_t)(bn + r) * FF + k0 + c4]);
            Bs[c4 + 0][r] = v.x; Bs[c4 + 1][r] = v.y;
            Bs[c4 + 2][r] = v.z; Bs[c4 + 3][r] = v.w;
        }
        __syncthreads();

        #pragma unroll
        for (int k = 0; k < BK; k++) {
            float ra[4], rb[4];
            {
                float4 v = *reinterpret_cast<const float4*>(&As[k][ty * 4]);
                ra[0] = v.x; ra[1] = v.y; ra[2] = v.z; ra[3] = v.w;
            }
            {
                float4 v = *reinterpret_cast<const float4*>(&Bs[k][tx * 4]);
                rb[0] = v.x; rb[1] = v.y; rb[2] = v.z; rb[3] = v.w;
            }
            #pragma unroll
            for (int i = 0; i < 4; i++)
                #pragma unroll
                for (int j = 0; j < 4; j++)
                    acc[i][j] = fmaf(ra[i], rb[j], acc[i][j]);
        }
        __syncthreads();
    }

    #pragma unroll
    for (int i = 0; i < 4; i++) {
        const size_t row = (size_t)(bm + ty * 4 + i) * DD + bn + tx * 4;
        *reinterpret_cast<float4*>(&g_down[row]) =
            make_float4(acc[i][0], acc[i][1], acc[i][2], acc[i][3]);
    }
}

// ------------------------------------------------------------------
// K7: epilogue — weighted mix of (down base + LoRA down) over 2 slots
// grid = TT blocks, 256 threads
// ------------------------------------------------------------------
__global__ __launch_bounds__(256) void k_epilogue(
    const float* __restrict__ b2, float* __restrict__ out)
{
    const int t = blockIdx.x, tid = threadIdx.x;

    __shared__ float c2s[KK][RR];
    __shared__ float ws[KK];
    __shared__ int es[KK];
    if (tid < KK * RR) c2s[tid >> 4][tid & 15] =
        g_c2[(size_t)(t * 2 + (tid >> 4)) * RR + (tid & 15)];
    if (tid < KK) { ws[tid] = g_ew[t * 2 + tid]; es[tid] = g_eidx[t * 2 + tid]; }
    __syncthreads();

    for (int d = tid; d < DD; d += 256) {
        float acc = 0.f;
        #pragma unroll
        for (int s = 0; s < KK; s++) {
            const float base = g_down[(size_t)(t * 2 + s) * DD + d];
            const float4* B2 = reinterpret_cast<const float4*>(
                b2 + ((size_t)es[s] * DD + d) * RR);
            float l = 0.f;
            #pragma unroll
            for (int q = 0; q < 4; q++) {
                float4 v = B2[q];
                l += v.x * c2s[s][q * 4] + v.y * c2s[s][q * 4 + 1]
                   + v.z * c2s[s][q * 4 + 2] + v.w * c2s[s][q * 4 + 3];
            }
            acc += ws[s] * (base + SCALE * l);
        }
        out[(size_t)t * DD + d] = acc;
    }
}

// ------------------------------------------------------------------
// Launch — kernel launches ONLY (maximally graph-capture safe)
// ------------------------------------------------------------------
extern "C" void kernel_launch(void* const* d_in, const int* in_sizes, int n_in,
                              void* d_out, int out_size)
{
    const float* x     = (const float*)d_in[0];
    const float* normw = (const float*)d_in[1];
    const float* w1    = (const float*)d_in[2];
    const float* w3    = (const float*)d_in[3];
    const float* w2    = (const float*)d_in[4];
    const float* gatew = (const float*)d_in[5];
    const float* a1    = (const float*)d_in[6];
    const float* b1    = (const float*)d_in[7];
    const float* a3    = (const float*)d_in[8];
    const float* b3    = (const float*)d_in[9];
    const float* a2    = (const float*)d_in[10];
    const float* b2    = (const float*)d_in[11];
    float* out = (float*)d_out;

    // 1. RMSNorm + router
    k_norm_route<<<TT, 256>>>(x, normw, gatew);

    // 2. Up-proj base GEMM: [512,1024] @ [8192,1024]^T -> g_base
    k_gemm_up<<<dim3((2 * FF) / 128, TT / 128), 256>>>(w1, w3);

    // 3. Up LoRA coefficients
    k_lora_up_coeff<<<TT, 256>>>(a1, a3);

    // 4. SwiGLU activation with LoRA deltas
    k_act<<<TT * KK, 256>>>(b1, b3);

    // 5. Down LoRA coefficients
    k_lora_down_coeff<<<TT * KK, 256>>>(a2);

    // 6. Down-proj base GEMM: [1024,4096] @ [4096(K) rows of w2=1024]^T
    k_gemm_down<<<dim3(DD / 64, (TT * KK) / 64), 256>>>(w2);

    // 7. Weighted mix + down LoRA
    k_epilogue<<<TT, 256>>>(b2, out);
}